// round 4
// baseline (speedup 1.0000x reference)
#include <cuda_runtime.h>
#include <climits>

// ---- problem-size caps (ref: N=100000, E=1600000, G=512, F=128) ----
#define MAXN 131072
#define MAXG 4096
#define MAXB 256   // max resident blocks we support

// scratch (no cudaMalloc allowed)
__device__ float g_dot[MAXN];   // x@W per node
__device__ int   g_cnt[MAXN];   // in-degree (deg = cnt+1)
__device__ float g_u[MAXN];     // gather source of current hop
__device__ float g_t[MAXN];     // accumulator of current hop
__device__ float g_dinv[MAXN];  // 1/deg
__device__ float g_dis[MAXN];   // deg^-1/2
__device__ float g_sum[MAXG];
__device__ int   g_gcnt[MAXG];

// software grid barrier state (reset to 0 at end of every launch)
__device__ volatile int g_arr[MAXB];
__device__ volatile int g_gen;

// distributed-slot grid barrier: no atomic hot spot.
// each block posts `phase` to its own slot; block 0 polls all slots then
// publishes `phase` to g_gen; others spin on g_gen.
__device__ __forceinline__ void gsync(int phase, int nb) {
    __syncthreads();
    __threadfence();
    if (blockIdx.x == 0) {
        for (int s = 1 + threadIdx.x; s < nb; s += blockDim.x)
            while (g_arr[s] < phase) { }
        __syncthreads();
        if (threadIdx.x == 0) { __threadfence(); g_gen = phase; }
    } else if (threadIdx.x == 0) {
        g_arr[blockIdx.x] = phase;
        while (g_gen < phase) { }
    }
    __syncthreads();
    __threadfence();
}

// end-of-launch reset so the next graph replay starts from a clean barrier.
// safe: a block only zeroes its slot after passing the final gsync, which
// block 0 can only have released after finishing its slot polls.
__device__ __forceinline__ void greset(int nb) {
    __syncthreads();
    if (threadIdx.x == 0) {
        if (blockIdx.x != 0) {
            g_arr[blockIdx.x] = 0;
        } else {
            for (int s = 1; s < nb; s++) while (g_arr[s] != 0) { }
            __threadfence();
            g_gen = 0;
        }
    }
}

__global__ void __launch_bounds__(1024, 1)
sgconv_fused(const float* __restrict__ x, const float* __restrict__ W,
             const float* __restrict__ bias,
             const int* __restrict__ row, const int* __restrict__ col,
             const int* __restrict__ batch,
             float* __restrict__ out,
             int n, int F, int E, int G, int nb) {
    const int tid    = blockIdx.x * blockDim.x + threadIdx.x;
    const int nth    = gridDim.x * blockDim.x;
    const int lane   = threadIdx.x & 31;
    const int warp   = tid >> 5;
    const int nwarps = nth >> 5;
    const bool vec4  = ((E & 3) == 0);
    const int  E4    = E >> 2;
    int phase = 0;

    // ---- PH_A: zero scratch ----
    for (int i = tid; i < n; i += nth) g_cnt[i] = 0;
    for (int i = tid; i < G; i += nth) { g_sum[i] = 0.0f; g_gcnt[i] = 0; }
    gsync(++phase, nb);

    // ---- PH_B: degree count + per-graph counts + GEMV ----
    if (vec4) {
        for (int q = tid; q < E4; q += nth) {
            int4 c = reinterpret_cast<const int4*>(col)[q];
            atomicAdd(&g_cnt[c.x], 1); atomicAdd(&g_cnt[c.y], 1);
            atomicAdd(&g_cnt[c.z], 1); atomicAdd(&g_cnt[c.w], 1);
        }
    } else {
        for (int e = tid; e < E; e += nth) atomicAdd(&g_cnt[col[e]], 1);
    }

    // per-graph node counts (batch is sorted -> warp aggregation)
    for (int base = warp * 32; base < n; base += nwarps * 32) {
        int i = base + lane;
        int b = (i < n) ? batch[i] : -1;
        unsigned peers = __match_any_sync(0xffffffffu, b);
        if (b >= 0 && (int)(__ffs(peers) - 1) == lane)
            atomicAdd(&g_gcnt[b], __popc(peers));
    }

    // GEMV: dot[i] = x[i,:] @ W, one warp per node
    if (F == 128) {
        float4 wv = *reinterpret_cast<const float4*>(W + lane * 4);
        for (int node = warp; node < n; node += nwarps) {
            float4 xv = *reinterpret_cast<const float4*>(x + (size_t)node * 128 + lane * 4);
            float acc = xv.x * wv.x + xv.y * wv.y + xv.z * wv.z + xv.w * wv.w;
            #pragma unroll
            for (int o = 16; o; o >>= 1) acc += __shfl_xor_sync(0xffffffffu, acc, o);
            if (lane == 0) g_dot[node] = acc;
        }
    } else {
        for (int node = warp; node < n; node += nwarps) {
            const float* xr = x + (size_t)node * F;
            float acc = 0.0f;
            for (int j = lane; j < F; j += 32) acc += xr[j] * W[j];
            #pragma unroll
            for (int o = 16; o; o >>= 1) acc += __shfl_xor_sync(0xffffffffu, acc, o);
            if (lane == 0) g_dot[node] = acc;
        }
    }
    gsync(++phase, nb);

    // ---- PH_C: diagonal scalings, u0 = t0 = dis * dot ----
    for (int i = tid; i < n; i += nth) {
        float deg  = (float)(g_cnt[i] + 1);   // +1 self-loop
        float dinv = __frcp_rn(deg);
        float dis  = rsqrtf(deg);
        g_dinv[i] = dinv;
        g_dis[i]  = dis;
        float u = dis * g_dot[i];
        g_u[i] = u;
        g_t[i] = u;                            // self-loop term of hop 1
    }
    gsync(++phase, nb);

    // ---- 3 hops: t[col] += u[row]; between hops t *= dinv, u = t ----
    #pragma unroll
    for (int hop = 0; hop < 3; hop++) {
        if (vec4) {
            for (int q = tid; q < E4; q += nth) {
                int4 r = reinterpret_cast<const int4*>(row)[q];
                int4 c = reinterpret_cast<const int4*>(col)[q];
                float v0 = __ldg(&g_u[r.x]);
                float v1 = __ldg(&g_u[r.y]);
                float v2 = __ldg(&g_u[r.z]);
                float v3 = __ldg(&g_u[r.w]);
                atomicAdd(&g_t[c.x], v0);
                atomicAdd(&g_t[c.y], v1);
                atomicAdd(&g_t[c.z], v2);
                atomicAdd(&g_t[c.w], v3);
            }
        } else {
            for (int e = tid; e < E; e += nth)
                atomicAdd(&g_t[col[e]], __ldg(&g_u[row[e]]));
        }
        gsync(++phase, nb);
        if (hop < 2) {
            for (int i = tid; i < n; i += nth) {
                float v = g_t[i] * g_dinv[i];
                g_t[i] = v;
                g_u[i] = v;
            }
            gsync(++phase, nb);
        }
    }

    // ---- per-graph sums: segmented warp reduction (batch sorted) ----
    for (int base = warp * 32; base < n; base += nwarps * 32) {
        int i = base + lane;
        float v = (i < n) ? g_dis[i] * g_t[i] : 0.0f;
        int   b = (i < n) ? batch[i] : INT_MAX;
        #pragma unroll
        for (int o = 1; o < 32; o <<= 1) {
            float vv = __shfl_down_sync(0xffffffffu, v, o);
            int   bb = __shfl_down_sync(0xffffffffu, b, o);
            if (lane + o < 32 && bb == b) v += vv;
        }
        int bp = __shfl_up_sync(0xffffffffu, b, 1);
        if (i < n && (lane == 0 || bp != b)) atomicAdd(&g_sum[b], v);
    }
    gsync(++phase, nb);

    // ---- final: block 0 writes output ----
    if (blockIdx.x == 0) {
        for (int g = threadIdx.x; g < G; g += blockDim.x) {
            int c = g_gcnt[g];
            out[g] = (c > 0) ? (g_sum[g] / (float)c + bias[0]) : 0.0f;
        }
    }

    greset(nb);
}

extern "C" void kernel_launch(void* const* d_in, const int* in_sizes, int n_in,
                              void* d_out, int out_size) {
    const float* x     = (const float*)d_in[0];   // [N, F]
    const float* W     = (const float*)d_in[1];   // [F, 1]
    const float* b     = (const float*)d_in[2];   // [1]
    const int*   ei    = (const int*)d_in[3];     // [2, E]
    const int*   batch = (const int*)d_in[4];     // [N]

    int F = in_sizes[1];
    int n = in_sizes[4];
    int E = in_sizes[3] / 2;
    int G = out_size;

    const int* row = ei;       // edge_index[0]
    const int* col = ei + E;   // edge_index[1]

    int dev = 0;
    cudaGetDevice(&dev);
    int nsm = 148;
    cudaDeviceGetAttribute(&nsm, cudaDevAttrMultiProcessorCount, dev);
    int nb = nsm < MAXB ? nsm : MAXB;   // grid <= #SMs -> all blocks co-resident

    sgconv_fused<<<nb, 1024>>>(x, W, b, row, col, batch, (float*)d_out,
                               n, F, E, G, nb);
}